// round 2
// baseline (speedup 1.0000x reference)
#include <cuda_runtime.h>

// IntegrableMLP: out[b,:] = V^T * (df/dx) via one forward pass + one VJP:
//   forward: z0 = W0 x + b0 ; a0 = swish(z0), d0 = dswish(z0)
//            z1 = W1 a0 + b1; a1 = swish(z1), d1 = dswish(z1)
//            z2 = W2 a1 + b2; d2 = dswish(z2)
//   backward: u2 = V .* d2
//             u1 = (W2^T u2) .* d1
//             u0 = (W1^T u1) .* d0
//             out[:,n] = W0^T u0   (n = 0,1)
// swish(z) = z*sigmoid(z); dswish = sw + s*(1-sw)

#define N0 32
#define N1 32
#define N2 16

__global__ __launch_bounds__(128) void mlp_vjp_kernel(
    const float* __restrict__ inputs,
    const float* __restrict__ W0, const float* __restrict__ b0,
    const float* __restrict__ W1, const float* __restrict__ b1,
    const float* __restrict__ W2, const float* __restrict__ b2,
    const float* __restrict__ V,
    float* __restrict__ out, int B)
{
    // weights in shared; W1/W2 also stored transposed for the backward pass
    __shared__ float sW0[N0 * 2];        // [32][2]
    __shared__ float sb0[N0];
    __shared__ float sW1[N1 * N0];       // [32][32] row-major (out, in)
    __shared__ float sW1T[N0 * N1];      // [in][out]
    __shared__ float sb1[N1];
    __shared__ float sW2[N2 * N1];       // [16][32]
    __shared__ float sW2T[N1 * N2];      // [in=32][out=16]
    __shared__ float sb2[N2];
    __shared__ float sV[N2];

    const int tid = threadIdx.x;
    for (int i = tid; i < N0 * 2; i += blockDim.x) sW0[i] = W0[i];
    for (int i = tid; i < N0; i += blockDim.x)     sb0[i] = b0[i];
    for (int i = tid; i < N1 * N0; i += blockDim.x) {
        float w = W1[i];
        int j = i >> 5, k = i & 31;      // W1[j][k]
        sW1[i] = w;
        sW1T[k * N1 + j] = w;
    }
    for (int i = tid; i < N1; i += blockDim.x)     sb1[i] = b1[i];
    for (int i = tid; i < N2 * N1; i += blockDim.x) {
        float w = W2[i];
        int j = i >> 5, k = i & 31;      // W2[j][k]
        sW2[i] = w;
        sW2T[k * N2 + j] = w;
    }
    for (int i = tid; i < N2; i += blockDim.x) { sb2[i] = b2[i]; sV[i] = V[i]; }
    __syncthreads();

    const int idx = blockIdx.x * blockDim.x + tid;
    if (idx >= B) return;

    const float2 x = reinterpret_cast<const float2*>(inputs)[idx];

    float a[N0];      // current activations
    float d0[N0], d1[N1], u2[N2];

    // ---- layer 0 ----
    #pragma unroll
    for (int j = 0; j < N0; j++) {
        float z = fmaf(x.y, sW0[2 * j + 1], fmaf(x.x, sW0[2 * j], sb0[j]));
        float s = __fdividef(1.0f, 1.0f + __expf(-z));
        float sw = z * s;
        a[j] = sw;
        d0[j] = fmaf(s, 1.0f - sw, sw);
    }

    // ---- layer 1 ----
    float t[N1];
    #pragma unroll
    for (int j = 0; j < N1; j++) {
        float z = sb1[j];
        #pragma unroll
        for (int k = 0; k < N0; k++) z = fmaf(a[k], sW1[j * N0 + k], z);
        t[j] = z;
    }
    #pragma unroll
    for (int j = 0; j < N1; j++) {
        float z = t[j];
        float s = __fdividef(1.0f, 1.0f + __expf(-z));
        float sw = z * s;
        a[j] = sw;
        d1[j] = fmaf(s, 1.0f - sw, sw);
    }

    // ---- layer 2 (only d2 needed; fold V in immediately) ----
    #pragma unroll
    for (int j = 0; j < N2; j++) {
        float z = sb2[j];
        #pragma unroll
        for (int k = 0; k < N1; k++) z = fmaf(a[k], sW2[j * N1 + k], z);
        float s = __fdividef(1.0f, 1.0f + __expf(-z));
        float sw = z * s;
        float d2 = fmaf(s, 1.0f - sw, sw);
        u2[j] = sV[j] * d2;              // u2 = V .* d2
    }

    // ---- backward: u1 = (W2^T u2) .* d1 ----
    float u1[N1];
    #pragma unroll
    for (int k = 0; k < N1; k++) {
        float acc = 0.0f;
        #pragma unroll
        for (int j = 0; j < N2; j++) acc = fmaf(u2[j], sW2T[k * N2 + j], acc);
        u1[k] = acc * d1[k];
    }

    // ---- backward: u0 = (W1^T u1) .* d0 ----
    float u0[N0];
    #pragma unroll
    for (int k = 0; k < N0; k++) {
        float acc = 0.0f;
        #pragma unroll
        for (int j = 0; j < N1; j++) acc = fmaf(u1[j], sW1T[k * N1 + j], acc);
        u0[k] = acc * d0[k];
    }

    // ---- out[:,n] = W0^T u0 ----
    float o0 = 0.0f, o1 = 0.0f;
    #pragma unroll
    for (int j = 0; j < N0; j++) {
        o0 = fmaf(u0[j], sW0[2 * j], o0);
        o1 = fmaf(u0[j], sW0[2 * j + 1], o1);
    }

    reinterpret_cast<float2*>(out)[idx] = make_float2(o0, o1);
}

extern "C" void kernel_launch(void* const* d_in, const int* in_sizes, int n_in,
                              void* d_out, int out_size)
{
    const float* inputs = (const float*)d_in[0];
    const float* W0 = (const float*)d_in[1];
    const float* b0 = (const float*)d_in[2];
    const float* W1 = (const float*)d_in[3];
    const float* b1 = (const float*)d_in[4];
    const float* W2 = (const float*)d_in[5];
    const float* b2 = (const float*)d_in[6];
    const float* V  = (const float*)d_in[7];
    float* out = (float*)d_out;

    const int B = in_sizes[0] / 2;      // inputs is [B, 2]
    const int threads = 128;
    const int blocks = (B + threads - 1) / threads;
    mlp_vjp_kernel<<<blocks, threads>>>(inputs, W0, b0, W1, b1, W2, b2, V, out, B);
}